// round 15
// baseline (speedup 1.0000x reference)
#include <cuda_runtime.h>
#include <cuda_bf16.h>

#define BS    4
#define NH    8
#define SEQ   2048
#define DK    64
#define NP    129
#define TI    4          // i-rows per block == warps per block
#define PSTR2 130        // float2 stride for swT rows
#define HPSTR 264        // floats per head-pair row: 132 positions * 2
#define NT    128

#define TBL_WARP (4 * HPSTR)                 // 1056 floats per warp (4224 B)
#define SWT_BYTES (32 * PSTR2 * 8)           // 33280
#define SMEM_BYTES (SWT_BYTES + TI * TBL_WARP * 4)   // 50176

typedef unsigned long long ull;

__device__ __forceinline__ ull fma2(ull a, ull b, ull c) {
    ull d;
    asm("fma.rn.f32x2 %0, %1, %2, %3;" : "=l"(d) : "l"(a), "l"(b), "l"(c));
    return d;
}

__global__ void __launch_bounds__(NT, 4)
fused_kernel(const float* __restrict__ q,
             const int*   __restrict__ dist,
             const float* __restrict__ w,
             float*       __restrict__ out) {
    extern __shared__ char smem_raw[];
    float2* swT  = reinterpret_cast<float2*>(smem_raw);                // [32][PSTR2]
    float*  tblz = reinterpret_cast<float*>(smem_raw + SWT_BYTES);     // [TI][TBL_WARP]

    const int tid  = threadIdx.x;
    const int warp = tid >> 5;
    const int lane = tid & 31;
    const int bi   = blockIdx.x;             // 0..2047
    const int b    = bi >> 9;                // 512 blocks per batch
    const int i    = (bi & 511) * TI + warp; // this warp's row

    // ---- cooperative: load w transposed swT[k2][p]; pad p>=129 with 0
    {
        const float2* w2 = reinterpret_cast<const float2*>(w);
        for (int idx = tid; idx < 32 * PSTR2; idx += NT) {
            const int k2 = idx / PSTR2;
            const int p  = idx - k2 * PSTR2;
            float2 v = make_float2(0.f, 0.f);
            if (p < NP) v = w2[p * 32 + k2];
            swT[idx] = v;
        }
    }
    __syncthreads();   // the ONLY block-wide barrier

    float* tb = tblz + warp * TBL_WARP;      // this warp's private patch

    // ---- stage this warp's q row into the (currently dead) table patch:
    //      qsm[h*32 + k2] = (q[h][2k2], q[h][2k2+1])
    {
        float2* qsm = reinterpret_cast<float2*>(tb);
        const float2* qbase = reinterpret_cast<const float2*>(
            q + ((size_t)(b * NH) * SEQ + i) * DK);
        const size_t hstep = (size_t)SEQ * 32;      // head stride in float2
#pragma unroll
        for (int h = 0; h < NH; h++)
            qsm[h * 32 + lane] = qbase[h * hstep + lane];
    }
    __syncwarp();

    // ---- projection: this warp computes t[hp][p][2] for all heads/positions
    {
        const float2* qsm = reinterpret_cast<const float2*>(tb);

        ull acc[NH][4];
#pragma unroll
        for (int h = 0; h < NH; h++)
#pragma unroll
            for (int u = 0; u < 4; u++) acc[h][u] = 0ULL;

#pragma unroll 4
        for (int k2 = 0; k2 < 32; k2++) {
            const float2* wrow = swT + k2 * PSTR2;
            ull wv[4];
#pragma unroll
            for (int u = 0; u < 4; u++)
                wv[u] = *reinterpret_cast<const ull*>(wrow + lane + 32 * u);
#pragma unroll
            for (int h = 0; h < NH; h++) {
                const ull qv = *reinterpret_cast<const ull*>(qsm + h * 32 + k2);
#pragma unroll
                for (int u = 0; u < 4; u++)
                    acc[h][u] = fma2(qv, wv[u], acc[h][u]);
            }
        }

        // p=128 epilogue: lane==k2; reduce across lanes for each h
        float veps[NH];
        {
            const float2 wq = swT[lane * PSTR2 + 128];
#pragma unroll
            for (int h = 0; h < NH; h++) {
                const float2 qq = qsm[h * 32 + lane];
                float v = qq.x * wq.x + qq.y * wq.y;
#pragma unroll
                for (int o = 16; o > 0; o >>= 1)
                    v += __shfl_xor_sync(0xffffffffu, v, o);
                veps[h] = v;
            }
        }
        __syncwarp();      // all lanes done reading qsm; overwrite with table

        // table write: head-paired, STS.64 conflict-free
#pragma unroll
        for (int hp = 0; hp < 4; hp++) {
            float2* dst = reinterpret_cast<float2*>(tb + hp * HPSTR);
#pragma unroll
            for (int u = 0; u < 4; u++) {
                float2 a0 = *reinterpret_cast<float2*>(&acc[2 * hp][u]);
                float2 a1 = *reinterpret_cast<float2*>(&acc[2 * hp + 1][u]);
                dst[lane + 32 * u] = make_float2(a0.x + a0.y, a1.x + a1.y);
            }
            if (lane == 0)
                dst[128] = make_float2(veps[2 * hp], veps[2 * hp + 1]);
        }
    }
    __syncwarp();

    // ---- gather: out[b,h,i,j] = t[h>>1][min(dist[b,i,j],128)][h&1]
    {
        const int4* drow = reinterpret_cast<const int4*>(
            dist + ((size_t)(b * SEQ + i)) * SEQ);
        float4* out4 = reinterpret_cast<float4*>(out);
        const size_t o0  = ((size_t)(b * NH) * SEQ + i) * (SEQ / 4);
        const size_t HS4 = (size_t)SEQ * (SEQ / 4);

        int4 dv[4];
#pragma unroll
        for (int it = 0; it < 4; it++)
            dv[it] = __ldcs(&drow[it * 32 + lane]);

#pragma unroll
        for (int it = 0; it < 16; it++) {
            const int4 d = dv[it & 3];
            if (it + 4 < 16)
                dv[it & 3] = __ldcs(&drow[(it + 4) * 32 + lane]);

            const int pa = min(d.x, 128);
            const int pb = min(d.y, 128);
            const int pc = min(d.z, 128);
            const int pd = min(d.w, 128);
            const size_t ob = o0 + it * 32 + lane;

#pragma unroll
            for (int hp = 0; hp < 4; hp++) {
                const float2* tph = reinterpret_cast<const float2*>(tb + hp * HPSTR);
                const float2 l0 = tph[pa];
                const float2 l1 = tph[pb];
                const float2 l2 = tph[pc];
                const float2 l3 = tph[pd];
                __stcs(&out4[ob + (2 * hp) * HS4],
                       make_float4(l0.x, l1.x, l2.x, l3.x));
                __stcs(&out4[ob + (2 * hp + 1) * HS4],
                       make_float4(l0.y, l1.y, l2.y, l3.y));
            }
        }
    }
}

extern "C" void kernel_launch(void* const* d_in, const int* in_sizes, int n_in,
                              void* d_out, int out_size) {
    const float* q    = (const float*)d_in[0];
    const int*   dist = (const int*)  d_in[1];
    const float* w    = (const float*)d_in[2];
    float*       out  = (float*)d_out;

    cudaFuncSetAttribute(fused_kernel,
                         cudaFuncAttributeMaxDynamicSharedMemorySize, SMEM_BYTES);

    fused_kernel<<<BS * (SEQ / TI), NT, SMEM_BYTES>>>(q, dist, w, out);
}

// round 16
// speedup vs baseline: 1.0748x; 1.0748x over previous
#include <cuda_runtime.h>
#include <cuda_bf16.h>

#define BS    4
#define NH    8
#define SEQ   2048
#define DK    64
#define NP    129
#define PSTR2 130        // float2 stride for swT rows
#define HPSTR 264        // floats per head-pair row: 132 positions * 2
#define NT    128
#define NROWS (BS * SEQ)         // 8192 work items (one i-row each)

#define TBL_WARP (4 * HPSTR)                 // 1056 floats per warp (4224 B)
#define SWT_BYTES (32 * PSTR2 * 8)           // 33280
#define SMEM_BYTES (SWT_BYTES + 4 * TBL_WARP * 4)   // 50176

typedef unsigned long long ull;

__device__ unsigned int g_row_ctr;

__device__ __forceinline__ ull fma2(ull a, ull b, ull c) {
    ull d;
    asm("fma.rn.f32x2 %0, %1, %2, %3;" : "=l"(d) : "l"(a), "l"(b), "l"(c));
    return d;
}

__global__ void reset_ctr_kernel() { g_row_ctr = 0u; }

__global__ void __launch_bounds__(NT, 4)
fused_kernel(const float* __restrict__ q,
             const int*   __restrict__ dist,
             const float* __restrict__ w,
             float*       __restrict__ out) {
    extern __shared__ char smem_raw[];
    float2* swT  = reinterpret_cast<float2*>(smem_raw);                // [32][PSTR2]
    float*  tblz = reinterpret_cast<float*>(smem_raw + SWT_BYTES);     // [4][TBL_WARP]

    const int tid  = threadIdx.x;
    const int warp = tid >> 5;
    const int lane = tid & 31;

    // ---- one-time per CTA: load w transposed swT[k2][p]; pad p>=129 with 0
    {
        const float2* w2 = reinterpret_cast<const float2*>(w);
        for (int idx = tid; idx < 32 * PSTR2; idx += NT) {
            const int k2 = idx / PSTR2;
            const int p  = idx - k2 * PSTR2;
            float2 v = make_float2(0.f, 0.f);
            if (p < NP) v = w2[p * 32 + k2];
            swT[idx] = v;
        }
    }
    __syncthreads();   // the ONLY block-wide barrier

    float* tb = tblz + warp * TBL_WARP;      // this warp's private patch

    // ---- per-warp dynamic row loop
    for (;;) {
        unsigned int row;
        if (lane == 0) row = atomicAdd(&g_row_ctr, 1u);
        row = __shfl_sync(0xffffffffu, row, 0);
        if (row >= NROWS) break;

        const int b = row >> 11;             // / SEQ
        const int i = row & (SEQ - 1);

        // ---- stage this warp's q row into the (currently dead) table patch
        {
            float2* qsm = reinterpret_cast<float2*>(tb);
            const float2* qbase = reinterpret_cast<const float2*>(
                q + ((size_t)(b * NH) * SEQ + i) * DK);
            const size_t hstep = (size_t)SEQ * 32;      // head stride in float2
#pragma unroll
            for (int h = 0; h < NH; h++)
                qsm[h * 32 + lane] = qbase[h * hstep + lane];
        }
        __syncwarp();

        // ---- projection: t[hp][p][2] for all heads/positions
        {
            const float2* qsm = reinterpret_cast<const float2*>(tb);

            ull acc[NH][4];
#pragma unroll
            for (int h = 0; h < NH; h++)
#pragma unroll
                for (int u = 0; u < 4; u++) acc[h][u] = 0ULL;

#pragma unroll 4
            for (int k2 = 0; k2 < 32; k2++) {
                const float2* wrow = swT + k2 * PSTR2;
                ull wv[4];
#pragma unroll
                for (int u = 0; u < 4; u++)
                    wv[u] = *reinterpret_cast<const ull*>(wrow + lane + 32 * u);
#pragma unroll
                for (int h = 0; h < NH; h++) {
                    const ull qv = *reinterpret_cast<const ull*>(qsm + h * 32 + k2);
#pragma unroll
                    for (int u = 0; u < 4; u++)
                        acc[h][u] = fma2(qv, wv[u], acc[h][u]);
                }
            }

            // p=128 epilogue: lane==k2; reduce across lanes for each h
            float veps[NH];
            {
                const float2 wq = swT[lane * PSTR2 + 128];
#pragma unroll
                for (int h = 0; h < NH; h++) {
                    const float2 qq = qsm[h * 32 + lane];
                    float v = qq.x * wq.x + qq.y * wq.y;
#pragma unroll
                    for (int o = 16; o > 0; o >>= 1)
                        v += __shfl_xor_sync(0xffffffffu, v, o);
                    veps[h] = v;
                }
            }
            __syncwarp();      // all lanes done reading qsm; overwrite with table

            // table write: head-paired, STS.64 conflict-free
#pragma unroll
            for (int hp = 0; hp < 4; hp++) {
                float2* dst = reinterpret_cast<float2*>(tb + hp * HPSTR);
#pragma unroll
                for (int u = 0; u < 4; u++) {
                    float2 a0 = *reinterpret_cast<float2*>(&acc[2 * hp][u]);
                    float2 a1 = *reinterpret_cast<float2*>(&acc[2 * hp + 1][u]);
                    dst[lane + 32 * u] = make_float2(a0.x + a0.y, a1.x + a1.y);
                }
                if (lane == 0)
                    dst[128] = make_float2(veps[2 * hp], veps[2 * hp + 1]);
            }
        }
        __syncwarp();

        // ---- gather: out[b,h,i,j] = t[h>>1][min(dist[b,i,j],128)][h&1]
        {
            const int4* drow = reinterpret_cast<const int4*>(
                dist + ((size_t)(b * SEQ + i)) * SEQ);
            float4* out4 = reinterpret_cast<float4*>(out);
            const size_t o0  = ((size_t)(b * NH) * SEQ + i) * (SEQ / 4);
            const size_t HS4 = (size_t)SEQ * (SEQ / 4);

            int4 dv[4];
#pragma unroll
            for (int it = 0; it < 4; it++)
                dv[it] = __ldcs(&drow[it * 32 + lane]);

#pragma unroll
            for (int it = 0; it < 16; it++) {
                const int4 d = dv[it & 3];
                if (it + 4 < 16)
                    dv[it & 3] = __ldcs(&drow[(it + 4) * 32 + lane]);

                const int pa = min(d.x, 128);
                const int pb = min(d.y, 128);
                const int pc = min(d.z, 128);
                const int pd = min(d.w, 128);
                const size_t ob = o0 + it * 32 + lane;

#pragma unroll
                for (int hp = 0; hp < 4; hp++) {
                    const float2* tph = reinterpret_cast<const float2*>(tb + hp * HPSTR);
                    const float2 l0 = tph[pa];
                    const float2 l1 = tph[pb];
                    const float2 l2 = tph[pc];
                    const float2 l3 = tph[pd];
                    __stcs(&out4[ob + (2 * hp) * HS4],
                           make_float4(l0.x, l1.x, l2.x, l3.x));
                    __stcs(&out4[ob + (2 * hp + 1) * HS4],
                           make_float4(l0.y, l1.y, l2.y, l3.y));
                }
            }
        }
        __syncwarp();      // row done; table patch reusable as q staging
    }
}

extern "C" void kernel_launch(void* const* d_in, const int* in_sizes, int n_in,
                              void* d_out, int out_size) {
    const float* q    = (const float*)d_in[0];
    const int*   dist = (const int*)  d_in[1];
    const float* w    = (const float*)d_in[2];
    float*       out  = (float*)d_out;

    cudaFuncSetAttribute(fused_kernel,
                         cudaFuncAttributeMaxDynamicSharedMemorySize, SMEM_BYTES);

    int dev = 0, nsm = 148;
    cudaGetDevice(&dev);
    cudaDeviceGetAttribute(&nsm, cudaDevAttrMultiProcessorCount, dev);

    reset_ctr_kernel<<<1, 1>>>();
    fused_kernel<<<nsm * 4, NT, SMEM_BYTES>>>(q, dist, w, out);
}